// round 10
// baseline (speedup 1.0000x reference)
#include <cuda_runtime.h>
#include <cuda_bf16.h>
#include <math.h>

// ---------------- problem constants ----------------
#define Bb   2
#define Ss   1024
#define Dm   2560
#define Hh   32
#define HD   80
#define BS   32
#define NBLK 32
#define KTOP 16
#define BH   (Bb*Hh)          // 64
#define ROWS (Bb*Ss)          // 2048
#define SCALE 0.11180339887498949f   // 80^-0.5

#define ACT_NONE 0
#define ACT_GELU 1

// ---------------- scratch (static device globals; no allocations) ------------
__device__ float    g_q[ROWS*Dm];
__device__ float    g_k[ROWS*Dm];
__device__ float    g_v[ROWS*Dm];
__device__ float    g_gh[ROWS*(Dm/2)];
__device__ float    g_gates[ROWS*3];
__device__ float    g_tb[2*BH*NBLK*Dm];        // [4096, 2560]
__device__ float    g_h1[2*BH*NBLK*320];       // [4096, 320]
__device__ float    g_kcvc[2*BH*NBLK*HD];      // kc rows 0..2047, vc rows 2048..4095
__device__ float    g_scores[(size_t)BH*Ss*Ss];// 268 MB
__device__ unsigned g_mask[BH*Ss];
__device__ float    g_comb[ROWS*Dm];

__device__ __forceinline__ float gelu_exact(float x) {
    return 0.5f * x * (1.0f + erff(x * 0.70710678118654752440f));
}

// =====================================================================
// SIMT fp32 tile (Wq, Wk) — byte-identical math to validated kernel.
// 128x128 tile, single fmaf chain over ascending k.
// =====================================================================
__device__ __forceinline__ void simt_tile(
    const float* __restrict__ A, const float* __restrict__ B,
    const float* __restrict__ bias, float* __restrict__ C,
    int N, int K, int m0, int n0, int act, int tid, char* smraw)
{
    float (*As)[132] = reinterpret_cast<float(*)[132]>(smraw);
    float (*Bs)[132] = reinterpret_cast<float(*)[132]>(smraw + 16 * 132 * sizeof(float));
    const int tx = tid & 15, ty = tid >> 4;

    float acc[8][8] = {};

    for (int k0 = 0; k0 < K; k0 += 16) {
        #pragma unroll
        for (int r = 0; r < 2; r++) {
            int idx = r * 256 + tid;
            int m = idx >> 2, k4 = (idx & 3) * 4;
            float4 f = *reinterpret_cast<const float4*>(&A[(size_t)(m0 + m) * K + k0 + k4]);
            As[k4 + 0][m] = f.x;
            As[k4 + 1][m] = f.y;
            As[k4 + 2][m] = f.z;
            As[k4 + 3][m] = f.w;
        }
        #pragma unroll
        for (int r = 0; r < 2; r++) {
            int idx = r * 256 + tid;
            int k = idx >> 5, n4 = (idx & 31) * 4;
            float4 f = *reinterpret_cast<const float4*>(&B[(size_t)(k0 + k) * N + n0 + n4]);
            *reinterpret_cast<float4*>(&Bs[k][n4]) = f;
        }
        __syncthreads();

        #pragma unroll
        for (int kk = 0; kk < 16; kk++) {
            float a[8], b[8];
            *reinterpret_cast<float4*>(&a[0]) = *reinterpret_cast<const float4*>(&As[kk][ty * 4]);
            *reinterpret_cast<float4*>(&a[4]) = *reinterpret_cast<const float4*>(&As[kk][64 + ty * 4]);
            *reinterpret_cast<float4*>(&b[0]) = *reinterpret_cast<const float4*>(&Bs[kk][tx * 4]);
            *reinterpret_cast<float4*>(&b[4]) = *reinterpret_cast<const float4*>(&Bs[kk][64 + tx * 4]);
            #pragma unroll
            for (int i = 0; i < 8; i++)
                #pragma unroll
                for (int j = 0; j < 8; j++)
                    acc[i][j] = fmaf(a[i], b[j], acc[i][j]);
        }
        __syncthreads();
    }

    #pragma unroll
    for (int i = 0; i < 8; i++) {
        int row = m0 + ((i < 4) ? (ty * 4 + i) : (64 + ty * 4 + i - 4));
        #pragma unroll
        for (int jg = 0; jg < 2; jg++) {
            int col = n0 + jg * 64 + tx * 4;
            float4 o;
            float* oc = &o.x;
            #pragma unroll
            for (int jj = 0; jj < 4; jj++) {
                float v = acc[i][jg * 4 + jj] + bias[col + jj];
                if (act == ACT_GELU) v = gelu_exact(v);
                oc[jj] = v;
            }
            *reinterpret_cast<float4*>(&C[(size_t)row * N + col]) = o;
        }
    }
}

// =====================================================================
// bf16x2 tensor-core tile (smooth paths) — byte-identical to round 9.
// =====================================================================
__device__ __forceinline__ void split_pack(float x, float y, unsigned& hi, unsigned& lo) {
    __nv_bfloat16 hx = __float2bfloat16(x);
    __nv_bfloat16 hy = __float2bfloat16(y);
    float rx = x - __bfloat162float(hx);
    float ry = y - __bfloat162float(hy);
    __nv_bfloat162 h = __halves2bfloat162(hx, hy);
    __nv_bfloat162 l = __halves2bfloat162(__float2bfloat16(rx), __float2bfloat16(ry));
    hi = *reinterpret_cast<unsigned*>(&h);
    lo = *reinterpret_cast<unsigned*>(&l);
}

#define MMA_BF16(C, Ar, Br)                                              \
    asm volatile(                                                        \
        "mma.sync.aligned.m16n8k16.row.col.f32.bf16.bf16.f32 "           \
        "{%0,%1,%2,%3},{%4,%5,%6,%7},{%8,%9},{%0,%1,%2,%3};"             \
        : "+f"(C[0]), "+f"(C[1]), "+f"(C[2]), "+f"(C[3])                 \
        : "r"(Ar[0]), "r"(Ar[1]), "r"(Ar[2]), "r"(Ar[3]),                \
          "r"(Br[0]), "r"(Br[1]))

#define MMA_SMEM_BYTES 37888   // (2*128*20 + 2*16*136) * 4

__device__ __forceinline__ void mma_tile(
    const float* __restrict__ Ap, const float* __restrict__ Bp,
    const float* __restrict__ bias, float* __restrict__ Cp,
    int N, int K, int lda, int ldb, int ldc,
    int m0, int n0, float alpha, int act, int beta1, int tid, char* smraw)
{
    unsigned* Ahi = reinterpret_cast<unsigned*>(smraw);       // [m][k2] stride 20
    unsigned* Alo = Ahi + 128 * 20;
    unsigned* Bhi = Alo + 128 * 20;                           // [k2][n] stride 136
    unsigned* Blo = Bhi + 16 * 136;

    const int warp = tid >> 5, lane = tid & 31;
    const int wm = warp & 1, wn = warp >> 1;          // 2 x 4 warps
    const int mBase = wm * 64, nBase = wn * 32;
    const int lr = lane >> 2, lc = lane & 3;

    float c[4][4][4] = {};

    for (int k0 = 0; k0 < K; k0 += 32) {
        #pragma unroll
        for (int r = 0; r < 4; r++) {
            int idx = r * 256 + tid;
            int m = idx >> 3, k4 = (idx & 7) * 4;
            float4 f = *reinterpret_cast<const float4*>(Ap + (size_t)(m0 + m) * lda + k0 + k4);
            unsigned h0, l0, h1, l1;
            split_pack(f.x, f.y, h0, l0);
            split_pack(f.z, f.w, h1, l1);
            int ad = m * 20 + (k4 >> 1);
            *reinterpret_cast<uint2*>(&Ahi[ad]) = make_uint2(h0, h1);
            *reinterpret_cast<uint2*>(&Alo[ad]) = make_uint2(l0, l1);
        }
        #pragma unroll
        for (int r = 0; r < 2; r++) {
            int idx = r * 256 + tid;
            int k2 = idx >> 5, n4 = (idx & 31) * 4;
            float4 f0 = make_float4(0.f, 0.f, 0.f, 0.f);
            float4 f1 = make_float4(0.f, 0.f, 0.f, 0.f);
            if (n0 + n4 < N) {
                f0 = *reinterpret_cast<const float4*>(Bp + (size_t)(k0 + 2 * k2) * ldb + n0 + n4);
                f1 = *reinterpret_cast<const float4*>(Bp + (size_t)(k0 + 2 * k2 + 1) * ldb + n0 + n4);
            }
            const float* e0 = &f0.x;
            const float* e1 = &f1.x;
            uint4 hv, lv;
            unsigned* hp = &hv.x;
            unsigned* lp = &lv.x;
            #pragma unroll
            for (int s = 0; s < 4; s++)
                split_pack(e0[s], e1[s], hp[s], lp[s]);
            int bd = k2 * 136 + n4;
            *reinterpret_cast<uint4*>(&Bhi[bd]) = hv;
            *reinterpret_cast<uint4*>(&Blo[bd]) = lv;
        }
        __syncthreads();

        #pragma unroll
        for (int ch = 0; ch < 2; ch++) {
            const int kk2 = ch * 8;
            unsigned ah[4][4], al[4][4];
            #pragma unroll
            for (int i = 0; i < 4; i++) {
                int r0 = (mBase + i * 16 + lr) * 20;
                int r8 = r0 + 8 * 20;
                ah[i][0] = Ahi[r0 + kk2 + lc];
                ah[i][1] = Ahi[r8 + kk2 + lc];
                ah[i][2] = Ahi[r0 + kk2 + lc + 4];
                ah[i][3] = Ahi[r8 + kk2 + lc + 4];
                al[i][0] = Alo[r0 + kk2 + lc];
                al[i][1] = Alo[r8 + kk2 + lc];
                al[i][2] = Alo[r0 + kk2 + lc + 4];
                al[i][3] = Alo[r8 + kk2 + lc + 4];
            }
            #pragma unroll
            for (int j = 0; j < 4; j++) {
                int cN = nBase + j * 8 + lr;
                unsigned bh[2], bl[2];
                bh[0] = Bhi[(kk2 + lc) * 136 + cN];
                bh[1] = Bhi[(kk2 + 4 + lc) * 136 + cN];
                bl[0] = Blo[(kk2 + lc) * 136 + cN];
                bl[1] = Blo[(kk2 + 4 + lc) * 136 + cN];
                #pragma unroll
                for (int i = 0; i < 4; i++) {
                    MMA_BF16(c[i][j], al[i], bh);
                    MMA_BF16(c[i][j], ah[i], bl);
                    MMA_BF16(c[i][j], ah[i], bh);
                }
            }
        }
        __syncthreads();
    }

    #pragma unroll
    for (int i = 0; i < 4; i++) {
        int row = m0 + mBase + i * 16 + lr;
        #pragma unroll
        for (int j = 0; j < 4; j++) {
            int col = n0 + nBase + j * 8 + lc * 2;
            if (col < N) {
                #pragma unroll
                for (int h = 0; h < 2; h++) {
                    int rr = row + h * 8;
                    float v0 = alpha * c[i][j][h * 2 + 0];
                    float v1 = alpha * c[i][j][h * 2 + 1];
                    if (bias) { v0 += bias[col]; v1 += bias[col + 1]; }
                    if (act == ACT_GELU) { v0 = gelu_exact(v0); v1 = gelu_exact(v1); }
                    float* p = Cp + (size_t)rr * ldc + col;
                    if (beta1) { p[0] += v0; p[1] += v1; }
                    else       { p[0] = v0;  p[1] = v1; }
                }
            }
        }
    }
}

// ---------------- scores tile (SIMT fp32, validated numerics) ----------------
__device__ __forceinline__ void scores_tile(
    const float* __restrict__ q, const float* __restrict__ k,
    float* __restrict__ scores, int bh, int i0, int j0, int tid, char* smraw)
{
    float (*Qs)[81] = reinterpret_cast<float(*)[81]>(smraw);
    float (*Ks)[81] = reinterpret_cast<float(*)[81]>(smraw + 64 * 81 * sizeof(float));
    int b = bh >> 5, h = bh & 31;
    int tx = tid & 15, ty = tid >> 4;

    for (int e = tid; e < 64 * 80; e += 256) {
        int r = e / 80, c = e % 80;
        Qs[r][c] = q[((size_t)(b * Ss + i0 + r)) * Dm + h * HD + c];
        Ks[r][c] = k[((size_t)(b * Ss + j0 + r)) * Dm + h * HD + c];
    }
    __syncthreads();

    float acc[4][4] = {};
    #pragma unroll 8
    for (int kk = 0; kk < 80; kk++) {
        float a[4], bb[4];
        #pragma unroll
        for (int i = 0; i < 4; i++) a[i] = Qs[ty * 4 + i][kk];
        #pragma unroll
        for (int j = 0; j < 4; j++) bb[j] = Ks[tx * 4 + j][kk];
        #pragma unroll
        for (int i = 0; i < 4; i++)
            #pragma unroll
            for (int j = 0; j < 4; j++)
                acc[i][j] = fmaf(a[i], bb[j], acc[i][j]);
    }
    #pragma unroll
    for (int i = 0; i < 4; i++)
        #pragma unroll
        for (int j = 0; j < 4; j++)
            scores[((size_t)bh * Ss + i0 + ty * 4 + i) * Ss + j0 + tx * 4 + j] =
                acc[i][j] * SCALE;
}

// ---------------- small bodies (identical numerics) ---------------------------
__device__ __forceinline__ void gather_body(
    const float* __restrict__ k, const float* __restrict__ v,
    const float* __restrict__ pos, float* __restrict__ tb, int r, int tid)
{
    const float* src = (r < 2048) ? k : v;
    int rr  = r & 2047;
    int b   = rr >> 10;
    int h   = (rr >> 5) & 31;
    int blk = rr & 31;
    for (int c = tid; c < Dm; c += 256) {
        int i = c / HD, d = c % HD;
        int s = blk * BS + i;
        tb[(size_t)r * Dm + c] =
            src[((size_t)(b * Ss + s)) * Dm + h * HD + d] + pos[c];
    }
}

__device__ __forceinline__ void gates_body(
    const float* __restrict__ gh, const float* __restrict__ W2,
    const float* __restrict__ b2, float* __restrict__ gates, int w, int lane)
{
    if (w >= ROWS * 3) return;
    int row = w / 3, j = w % 3;
    const float* g = gh + (size_t)row * (Dm / 2);
    float acc = 0.f;
    for (int c = lane; c < Dm / 2; c += 32) acc = fmaf(g[c], W2[c * 3 + j], acc);
    #pragma unroll
    for (int o = 16; o > 0; o >>= 1) acc += __shfl_xor_sync(0xffffffffu, acc, o);
    if (lane == 0) gates[w] = 1.f / (1.f + expf(-(acc + b2[j])));
}

__device__ __forceinline__ void outc_body(
    const float* __restrict__ q, const float* __restrict__ kcvc,
    const float* __restrict__ gates, float* __restrict__ combined, int idx)
{
    if (idx >= BH * Ss) return;
    int bh = idx >> 10;
    int s  = idx & 1023;
    int b  = bh >> 5, h = bh & 31;
    const float* qrow = q + ((size_t)(b * Ss + s)) * Dm + h * HD;
    const float* kc   = kcvc + (size_t)bh * NBLK * HD;
    const float* vc   = kcvc + (size_t)2048 * HD + (size_t)bh * NBLK * HD;

    float logit[NBLK];
    float mx = -INFINITY;
    #pragma unroll
    for (int j = 0; j < NBLK; j++) {
        float acc = 0.f;
        const float* kr = kc + j * HD;
        for (int d = 0; d < HD; d++) acc = fmaf(qrow[d], kr[d], acc);
        acc *= SCALE;
        logit[j] = acc;
        mx = fmaxf(mx, acc);
    }
    float Z = 0.f;
    #pragma unroll
    for (int j = 0; j < NBLK; j++) { logit[j] = expf(logit[j] - mx); Z += logit[j]; }
    float g0 = gates[(b * Ss + s) * 3 + 0];
    float c0 = g0 / Z;
    float* out = combined + ((size_t)(b * Ss + s)) * Dm + h * HD;
    for (int d = 0; d < HD; d++) {
        float acc = 0.f;
        #pragma unroll
        for (int j = 0; j < NBLK; j++) acc = fmaf(logit[j], vc[j * HD + d], acc);
        out[d] = c0 * acc;
    }
}

__device__ __forceinline__ void mask_body(
    const float* __restrict__ scores, unsigned* __restrict__ mask, int idx)
{
    int gw   = idx >> 5;
    int lane = idx & 31;
    if (gw >= BH * Ss) return;
    const float* row = scores + (size_t)gw * Ss;
    float s = 0.f;
    for (int t = 0; t < BS; t++) s += row[lane * BS + t];

    unsigned m = 0;
    float val = s;
    for (int it = 0; it < KTOP; it++) {
        float bv = val; int bi = lane;
        #pragma unroll
        for (int off = 16; off > 0; off >>= 1) {
            float ov = __shfl_xor_sync(0xffffffffu, bv, off);
            int   oi = __shfl_xor_sync(0xffffffffu, bi, off);
            if (ov > bv || (ov == bv && oi < bi)) { bv = ov; bi = oi; }
        }
        m |= (1u << bi);
        if (lane == bi) val = -INFINITY;
    }
    if (lane == 0) mask[gw] = m;
}

__device__ __forceinline__ void weights_body(
    float* __restrict__ scores, const unsigned* __restrict__ mask,
    const float* __restrict__ gates, int row, int tid, char* smraw)
{
    float* sm  = reinterpret_cast<float*>(smraw);          // [1024]
    float* red = sm + Ss;                                  // [256]
    int bh  = row >> 10;
    int s   = row & 1023;
    int b   = bh >> 5;
    float* rp = scores + (size_t)row * Ss;
    unsigned msk = mask[row];

    float lmw = -INFINITY;
    for (int c = tid; c < Ss; c += 256) {
        float x = rp[c];
        sm[c] = x;
        lmw = fmaxf(lmw, x);
    }
    red[tid] = lmw; __syncthreads();
    for (int st = 128; st > 0; st >>= 1) {
        if (tid < st) red[tid] = fmaxf(red[tid], red[tid + st]);
        __syncthreads();
    }
    float mw = red[0]; __syncthreads();

    float lzw = 0.f, lzs = 0.f;
    for (int c = tid; c < Ss; c += 256) {
        float ew = expf(sm[c] - mw);
        sm[c] = ew;
        lzw += ew;
        if ((msk >> (c >> 5)) & 1u) lzs += ew;
    }
    red[tid] = lzw; __syncthreads();
    for (int st = 128; st > 0; st >>= 1) {
        if (tid < st) red[tid] += red[tid + st];
        __syncthreads();
    }
    float Zw = red[0]; __syncthreads();
    red[tid] = lzs; __syncthreads();
    for (int st = 128; st > 0; st >>= 1) {
        if (tid < st) red[tid] += red[tid + st];
        __syncthreads();
    }
    float Zs = red[0]; __syncthreads();

    float g1 = gates[(b * Ss + s) * 3 + 1];
    float g2 = gates[(b * Ss + s) * 3 + 2];
    float cw = g2 / Zw;
    float cs = g1 / Zs;
    for (int c = tid; c < Ss; c += 256) {
        float ew = sm[c];
        float w = cw * ew;
        if ((msk >> (c >> 5)) & 1u) w += cs * ew;
        rp[c] = w;
    }
}

// =====================================================================
// FAT kernels — block-type dispatch for pipe-level overlap.
// =====================================================================

// FAT1: Wq/Wk SIMT (640 tiles) interleaved 4:3 with Wv/gate MMA (480 tiles)
__global__ void __launch_bounds__(256, 2) fat1_kernel(
    const float* __restrict__ hidden,
    const float* __restrict__ Wq, const float* __restrict__ bq,
    const float* __restrict__ Wk, const float* __restrict__ bk,
    const float* __restrict__ Wv, const float* __restrict__ bv,
    const float* __restrict__ gW1, const float* __restrict__ gb1,
    float* __restrict__ q, float* __restrict__ k,
    float* __restrict__ v, float* __restrict__ gh)
{
    __shared__ __align__(16) char smraw[MMA_SMEM_BYTES];
    int bid = blockIdx.x, tid = threadIdx.x;
    int grp = bid / 7, rem = bid % 7;
    if (rem < 4) {
        int s = grp * 4 + rem;                   // 0..639 SIMT tiles
        if (s < 320)
            simt_tile(hidden, Wq, bq, q, Dm, Dm, (s / 20) * 128, (s % 20) * 128, ACT_NONE, tid, smraw);
        else {
            s -= 320;
            simt_tile(hidden, Wk, bk, k, Dm, Dm, (s / 20) * 128, (s % 20) * 128, ACT_NONE, tid, smraw);
        }
    } else {
        int m = grp * 3 + (rem - 4);             // 0..479 MMA tiles
        if (m < 320)
            mma_tile(hidden, Wv, bv, v, Dm, Dm, Dm, Dm, Dm,
                     (m / 20) * 128, (m % 20) * 128, 1.f, ACT_NONE, 0, tid, smraw);
        else {
            m -= 320;
            mma_tile(hidden, gW1, gb1, gh, Dm / 2, Dm, Dm, Dm / 2, Dm / 2,
                     (m / 10) * 128, (m % 10) * 128, 1.f, ACT_GELU, 0, tid, smraw);
        }
    }
}

// gather + gates
__global__ void __launch_bounds__(256) gg_kernel(
    const float* __restrict__ k, const float* __restrict__ v,
    const float* __restrict__ pos, float* __restrict__ tb,
    const float* __restrict__ gh, const float* __restrict__ W2,
    const float* __restrict__ b2, float* __restrict__ gates)
{
    int bid = blockIdx.x, tid = threadIdx.x;
    if (bid < 4096) gather_body(k, v, pos, tb, bid, tid);
    else            gates_body(gh, W2, b2, gates, (((bid - 4096) * 256 + tid) >> 5), tid & 31);
}

// FAT2: compW1 MMA (96 tiles) + scores SIMT (16384 tiles)
__global__ void __launch_bounds__(256, 2) fat2_kernel(
    const float* __restrict__ tb, const float* __restrict__ cW1,
    const float* __restrict__ cb1, float* __restrict__ h1,
    const float* __restrict__ q, const float* __restrict__ k,
    float* __restrict__ scores)
{
    __shared__ __align__(16) char smraw[64 * 81 * 8];   // 41472 >= MMA_SMEM_BYTES
    int bid = blockIdx.x, tid = threadIdx.x;
    if (bid < 96) {
        mma_tile(tb, cW1, cb1, h1, 320, Dm, Dm, 320, 320,
                 (bid / 3) * 128, (bid % 3) * 128, 1.f, ACT_GELU, 0, tid, smraw);
    } else {
        int sid = bid - 96;
        int j0 = (sid & 15) * 64;
        int i0 = ((sid >> 4) & 15) * 64;
        int bh = sid >> 8;
        scores_tile(q, k, scores, bh, i0, j0, tid, smraw);
    }
}

// compW2 MMA (32 tiles) + mask (8192 blocks)
__global__ void __launch_bounds__(256, 2) cm_kernel(
    const float* __restrict__ h1, const float* __restrict__ cW2,
    const float* __restrict__ cb2, float* __restrict__ kcvc,
    const float* __restrict__ scores, unsigned* __restrict__ mask)
{
    __shared__ __align__(16) char smraw[MMA_SMEM_BYTES];
    int bid = blockIdx.x, tid = threadIdx.x;
    if (bid < 32)
        mma_tile(h1, cW2, cb2, kcvc, HD, 320, 320, HD, HD,
                 bid * 128, 0, 1.f, ACT_NONE, 0, tid, smraw);
    else
        mask_body(scores, mask, (bid - 32) * 256 + tid);
}

// outc (256 blocks) + weights (65536 blocks)
__global__ void __launch_bounds__(256) ow_kernel(
    const float* __restrict__ q, const float* __restrict__ kcvc,
    const float* __restrict__ gates, float* __restrict__ combined,
    float* __restrict__ scores, const unsigned* __restrict__ mask)
{
    __shared__ __align__(16) char smraw[(Ss + 256) * 4];
    int bid = blockIdx.x, tid = threadIdx.x;
    if (bid < 256) outc_body(q, kcvc, gates, combined, bid * 256 + tid);
    else           weights_body(scores, mask, gates, bid - 256, tid, smraw);
}

// standalone batched MMA wrapper (PV, Wo)
__global__ void __launch_bounds__(256, 2) mma_gemm_g(
    const float* __restrict__ A, const float* __restrict__ B,
    const float* __restrict__ bias, float* __restrict__ C,
    int N, int K, int lda, int ldb, int ldc,
    long long sAz, long long sAb, long long sBz, long long sBb,
    long long sCz, long long sCb, float alpha, int act, int beta1)
{
    __shared__ __align__(16) char smraw[MMA_SMEM_BYTES];
    int z = blockIdx.z;
    const float* Ap = A + (size_t)z * sAz + (size_t)(z >> 5) * sAb;
    const float* Bp = B + (size_t)z * sBz + (size_t)(z >> 5) * sBb;
    float*       Cp = C + (size_t)z * sCz + (size_t)(z >> 5) * sCb;
    mma_tile(Ap, Bp, bias, Cp, N, K, lda, ldb, ldc,
             blockIdx.y * 128, blockIdx.x * 128, alpha, act, beta1,
             threadIdx.x, smraw);
}

// ---------------- host launch ------------------------------------------------
static void* symaddr(const void* sym) {
    void* p = nullptr;
    cudaGetSymbolAddress(&p, sym);
    return p;
}

extern "C" void kernel_launch(void* const* d_in, const int* in_sizes, int n_in,
                              void* d_out, int out_size)
{
    const float* hidden  = (const float*)d_in[0];
    const float* Wq      = (const float*)d_in[1];
    const float* bq      = (const float*)d_in[2];
    const float* Wk      = (const float*)d_in[3];
    const float* bk      = (const float*)d_in[4];
    const float* Wv      = (const float*)d_in[5];
    const float* bv      = (const float*)d_in[6];
    const float* Wo      = (const float*)d_in[7];
    const float* bo      = (const float*)d_in[8];
    const float* cpos    = (const float*)d_in[9];
    const float* cW1     = (const float*)d_in[10];
    const float* cb1     = (const float*)d_in[11];
    const float* cW2     = (const float*)d_in[12];
    const float* cb2     = (const float*)d_in[13];
    const float* gW1     = (const float*)d_in[14];
    const float* gb1     = (const float*)d_in[15];
    const float* gW2     = (const float*)d_in[16];
    const float* gb2     = (const float*)d_in[17];
    float* out = (float*)d_out;

    float*    q     = (float*)symaddr(g_q);
    float*    k     = (float*)symaddr(g_k);
    float*    v     = (float*)symaddr(g_v);
    float*    gh    = (float*)symaddr(g_gh);
    float*    gates = (float*)symaddr(g_gates);
    float*    tb    = (float*)symaddr(g_tb);
    float*    h1    = (float*)symaddr(g_h1);
    float*    kcvc  = (float*)symaddr(g_kcvc);
    float*    sc    = (float*)symaddr(g_scores);
    unsigned* msk   = (unsigned*)symaddr(g_mask);
    float*    comb  = (float*)symaddr(g_comb);

    const long long sQh = HD;                           // per-z (head) offset
    const long long sQb = (long long)Ss * Dm - 32 * HD; // per-batch extra

    // Phase 1: Wq/Wk (SIMT, top-k path) overlapped with Wv/gate (bf16 MMA)
    fat1_kernel<<<1120, 256>>>(hidden, Wq, bq, Wk, bk, Wv, bv, gW1, gb1, q, k, v, gh);

    // Phase 2: comp gather + gate sigmoid
    gg_kernel<<<4096 + 768, 256>>>(k, v, cpos, tb, gh, gW2, gb2, gates);

    // Phase 3: compW1 (MMA) overlapped with dense scores (SIMT, validated)
    fat2_kernel<<<96 + 16384, 256>>>(tb, cW1, cb1, h1, q, k, sc);

    // Phase 4: compW2 (MMA) + block top-k mask
    cm_kernel<<<32 + 8192, 256>>>(h1, cW2, cb2, kcvc, sc, msk);

    // Phase 5: compressed branch output + fused dual-softmax weights
    ow_kernel<<<256 + 65536, 256>>>(q, kcvc, gates, comb, sc, msk);

    // Phase 6: PV (batched, accumulate into comb)
    mma_gemm_g<<<dim3(1, Ss / 128, BH), 256>>>(
        sc, v, nullptr, comb, HD, Ss, Ss, Dm, Dm,
        (long long)Ss * Ss, 0, sQh, sQb, sQh, sQb, 1.f, ACT_NONE, 1);

    // Phase 7: output projection
    mma_gemm_g<<<dim3(Dm / 128, ROWS / 128, 1), 256>>>(
        comb, Wo, bo, out, Dm, Dm, Dm, Dm, Dm,
        0, 0, 0, 0, 0, 0, 1.f, ACT_NONE, 0);
}

// round 11
// speedup vs baseline: 1.0131x; 1.0131x over previous
#include <cuda_runtime.h>
#include <cuda_bf16.h>
#include <math.h>

// ---------------- problem constants ----------------
#define Bb   2
#define Ss   1024
#define Dm   2560
#define Hh   32
#define HD   80
#define BS   32
#define NBLK 32
#define KTOP 16
#define BH   (Bb*Hh)          // 64
#define ROWS (Bb*Ss)          // 2048
#define SCALE 0.11180339887498949f   // 80^-0.5

#define ACT_NONE 0
#define ACT_GELU 1

// ---------------- scratch (static device globals; no allocations) ------------
__device__ float    g_q[ROWS*Dm];
__device__ float    g_k[ROWS*Dm];
__device__ float    g_v[ROWS*Dm];
__device__ float    g_gh[ROWS*(Dm/2)];
__device__ float    g_gates[ROWS*3];
__device__ float    g_tb[2*BH*NBLK*Dm];        // [4096, 2560]
__device__ float    g_h1[2*BH*NBLK*320];       // [4096, 320]
__device__ float    g_kcvc[2*BH*NBLK*HD];      // kc rows 0..2047, vc rows 2048..4095
__device__ float    g_scores[(size_t)BH*Ss*Ss];// 268 MB
__device__ unsigned g_mask[BH*Ss];
__device__ float    g_comb[ROWS*Dm];

__device__ __forceinline__ float gelu_exact(float x) {
    return 0.5f * x * (1.0f + erff(x * 0.70710678118654752440f));
}

// =====================================================================
// SIMT fp32 tile (Wq, Wk) — byte-identical math to validated kernel.
// 128x128 tile, single fmaf chain over ascending k.
// =====================================================================
__device__ __forceinline__ void simt_tile(
    const float* __restrict__ A, const float* __restrict__ B,
    const float* __restrict__ bias, float* __restrict__ C,
    int N, int K, int m0, int n0, int act, int tid, char* smraw)
{
    float (*As)[132] = reinterpret_cast<float(*)[132]>(smraw);
    float (*Bs)[132] = reinterpret_cast<float(*)[132]>(smraw + 16 * 132 * sizeof(float));
    const int tx = tid & 15, ty = tid >> 4;

    float acc[8][8] = {};

    for (int k0 = 0; k0 < K; k0 += 16) {
        #pragma unroll
        for (int r = 0; r < 2; r++) {
            int idx = r * 256 + tid;
            int m = idx >> 2, k4 = (idx & 3) * 4;
            float4 f = *reinterpret_cast<const float4*>(&A[(size_t)(m0 + m) * K + k0 + k4]);
            As[k4 + 0][m] = f.x;
            As[k4 + 1][m] = f.y;
            As[k4 + 2][m] = f.z;
            As[k4 + 3][m] = f.w;
        }
        #pragma unroll
        for (int r = 0; r < 2; r++) {
            int idx = r * 256 + tid;
            int k = idx >> 5, n4 = (idx & 31) * 4;
            float4 f = *reinterpret_cast<const float4*>(&B[(size_t)(k0 + k) * N + n0 + n4]);
            *reinterpret_cast<float4*>(&Bs[k][n4]) = f;
        }
        __syncthreads();

        #pragma unroll
        for (int kk = 0; kk < 16; kk++) {
            float a[8], b[8];
            *reinterpret_cast<float4*>(&a[0]) = *reinterpret_cast<const float4*>(&As[kk][ty * 4]);
            *reinterpret_cast<float4*>(&a[4]) = *reinterpret_cast<const float4*>(&As[kk][64 + ty * 4]);
            *reinterpret_cast<float4*>(&b[0]) = *reinterpret_cast<const float4*>(&Bs[kk][tx * 4]);
            *reinterpret_cast<float4*>(&b[4]) = *reinterpret_cast<const float4*>(&Bs[kk][64 + tx * 4]);
            #pragma unroll
            for (int i = 0; i < 8; i++)
                #pragma unroll
                for (int j = 0; j < 8; j++)
                    acc[i][j] = fmaf(a[i], b[j], acc[i][j]);
        }
        __syncthreads();
    }

    #pragma unroll
    for (int i = 0; i < 8; i++) {
        int row = m0 + ((i < 4) ? (ty * 4 + i) : (64 + ty * 4 + i - 4));
        #pragma unroll
        for (int jg = 0; jg < 2; jg++) {
            int col = n0 + jg * 64 + tx * 4;
            float4 o;
            float* oc = &o.x;
            #pragma unroll
            for (int jj = 0; jj < 4; jj++) {
                float v = acc[i][jg * 4 + jj] + bias[col + jj];
                if (act == ACT_GELU) v = gelu_exact(v);
                oc[jj] = v;
            }
            *reinterpret_cast<float4*>(&C[(size_t)row * N + col]) = o;
        }
    }
}

// =====================================================================
// bf16x2 tensor-core tile (smooth paths) — byte-identical to round 9.
// =====================================================================
__device__ __forceinline__ void split_pack(float x, float y, unsigned& hi, unsigned& lo) {
    __nv_bfloat16 hx = __float2bfloat16(x);
    __nv_bfloat16 hy = __float2bfloat16(y);
    float rx = x - __bfloat162float(hx);
    float ry = y - __bfloat162float(hy);
    __nv_bfloat162 h = __halves2bfloat162(hx, hy);
    __nv_bfloat162 l = __halves2bfloat162(__float2bfloat16(rx), __float2bfloat16(ry));
    hi = *reinterpret_cast<unsigned*>(&h);
    lo = *reinterpret_cast<unsigned*>(&l);
}

#define MMA_BF16(C, Ar, Br)                                              \
    asm volatile(                                                        \
        "mma.sync.aligned.m16n8k16.row.col.f32.bf16.bf16.f32 "           \
        "{%0,%1,%2,%3},{%4,%5,%6,%7},{%8,%9},{%0,%1,%2,%3};"             \
        : "+f"(C[0]), "+f"(C[1]), "+f"(C[2]), "+f"(C[3])                 \
        : "r"(Ar[0]), "r"(Ar[1]), "r"(Ar[2]), "r"(Ar[3]),                \
          "r"(Br[0]), "r"(Br[1]))

#define MMA_SMEM_BYTES 37888   // (2*128*20 + 2*16*136) * 4

__device__ __forceinline__ void mma_tile(
    const float* __restrict__ Ap, const float* __restrict__ Bp,
    const float* __restrict__ bias, float* __restrict__ Cp,
    int N, int K, int lda, int ldb, int ldc,
    int m0, int n0, float alpha, int act, int beta1, int tid, char* smraw)
{
    unsigned* Ahi = reinterpret_cast<unsigned*>(smraw);       // [m][k2] stride 20
    unsigned* Alo = Ahi + 128 * 20;
    unsigned* Bhi = Alo + 128 * 20;                           // [k2][n] stride 136
    unsigned* Blo = Bhi + 16 * 136;

    const int warp = tid >> 5, lane = tid & 31;
    const int wm = warp & 1, wn = warp >> 1;          // 2 x 4 warps
    const int mBase = wm * 64, nBase = wn * 32;
    const int lr = lane >> 2, lc = lane & 3;

    float c[4][4][4] = {};

    for (int k0 = 0; k0 < K; k0 += 32) {
        #pragma unroll
        for (int r = 0; r < 4; r++) {
            int idx = r * 256 + tid;
            int m = idx >> 3, k4 = (idx & 7) * 4;
            float4 f = *reinterpret_cast<const float4*>(Ap + (size_t)(m0 + m) * lda + k0 + k4);
            unsigned h0, l0, h1, l1;
            split_pack(f.x, f.y, h0, l0);
            split_pack(f.z, f.w, h1, l1);
            int ad = m * 20 + (k4 >> 1);
            *reinterpret_cast<uint2*>(&Ahi[ad]) = make_uint2(h0, h1);
            *reinterpret_cast<uint2*>(&Alo[ad]) = make_uint2(l0, l1);
        }
        #pragma unroll
        for (int r = 0; r < 2; r++) {
            int idx = r * 256 + tid;
            int k2 = idx >> 5, n4 = (idx & 31) * 4;
            float4 f0 = make_float4(0.f, 0.f, 0.f, 0.f);
            float4 f1 = make_float4(0.f, 0.f, 0.f, 0.f);
            if (n0 + n4 < N) {
                f0 = *reinterpret_cast<const float4*>(Bp + (size_t)(k0 + 2 * k2) * ldb + n0 + n4);
                f1 = *reinterpret_cast<const float4*>(Bp + (size_t)(k0 + 2 * k2 + 1) * ldb + n0 + n4);
            }
            const float* e0 = &f0.x;
            const float* e1 = &f1.x;
            uint4 hv, lv;
            unsigned* hp = &hv.x;
            unsigned* lp = &lv.x;
            #pragma unroll
            for (int s = 0; s < 4; s++)
                split_pack(e0[s], e1[s], hp[s], lp[s]);
            int bd = k2 * 136 + n4;
            *reinterpret_cast<uint4*>(&Bhi[bd]) = hv;
            *reinterpret_cast<uint4*>(&Blo[bd]) = lv;
        }
        __syncthreads();

        #pragma unroll
        for (int ch = 0; ch < 2; ch++) {
            const int kk2 = ch * 8;
            unsigned ah[4][4], al[4][4];
            #pragma unroll
            for (int i = 0; i < 4; i++) {
                int r0 = (mBase + i * 16 + lr) * 20;
                int r8 = r0 + 8 * 20;
                ah[i][0] = Ahi[r0 + kk2 + lc];
                ah[i][1] = Ahi[r8 + kk2 + lc];
                ah[i][2] = Ahi[r0 + kk2 + lc + 4];
                ah[i][3] = Ahi[r8 + kk2 + lc + 4];
                al[i][0] = Alo[r0 + kk2 + lc];
                al[i][1] = Alo[r8 + kk2 + lc];
                al[i][2] = Alo[r0 + kk2 + lc + 4];
                al[i][3] = Alo[r8 + kk2 + lc + 4];
            }
            #pragma unroll
            for (int j = 0; j < 4; j++) {
                int cN = nBase + j * 8 + lr;
                unsigned bh[2], bl[2];
                bh[0] = Bhi[(kk2 + lc) * 136 + cN];
                bh[1] = Bhi[(kk2 + 4 + lc) * 136 + cN];
                bl[0] = Blo[(kk2 + lc) * 136 + cN];
                bl[1] = Blo[(kk2 + 4 + lc) * 136 + cN];
                #pragma unroll
                for (int i = 0; i < 4; i++) {
                    MMA_BF16(c[i][j], al[i], bh);
                    MMA_BF16(c[i][j], ah[i], bl);
                    MMA_BF16(c[i][j], ah[i], bh);
                }
            }
        }
        __syncthreads();
    }

    #pragma unroll
    for (int i = 0; i < 4; i++) {
        int row = m0 + mBase + i * 16 + lr;
        #pragma unroll
        for (int j = 0; j < 4; j++) {
            int col = n0 + nBase + j * 8 + lc * 2;
            if (col < N) {
                #pragma unroll
                for (int h = 0; h < 2; h++) {
                    int rr = row + h * 8;
                    float v0 = alpha * c[i][j][h * 2 + 0];
                    float v1 = alpha * c[i][j][h * 2 + 1];
                    if (bias) { v0 += bias[col]; v1 += bias[col + 1]; }
                    if (act == ACT_GELU) { v0 = gelu_exact(v0); v1 = gelu_exact(v1); }
                    float* p = Cp + (size_t)rr * ldc + col;
                    if (beta1) { p[0] += v0; p[1] += v1; }
                    else       { p[0] = v0;  p[1] = v1; }
                }
            }
        }
    }
}

// ---------------- scores tile (SIMT fp32, validated numerics) ----------------
__device__ __forceinline__ void scores_tile(
    const float* __restrict__ q, const float* __restrict__ k,
    float* __restrict__ scores, int bh, int i0, int j0, int tid, char* smraw)
{
    float (*Qs)[81] = reinterpret_cast<float(*)[81]>(smraw);
    float (*Ks)[81] = reinterpret_cast<float(*)[81]>(smraw + 64 * 81 * sizeof(float));
    int b = bh >> 5, h = bh & 31;
    int tx = tid & 15, ty = tid >> 4;

    for (int e = tid; e < 64 * 80; e += 256) {
        int r = e / 80, c = e % 80;
        Qs[r][c] = q[((size_t)(b * Ss + i0 + r)) * Dm + h * HD + c];
        Ks[r][c] = k[((size_t)(b * Ss + j0 + r)) * Dm + h * HD + c];
    }
    __syncthreads();

    float acc[4][4] = {};
    #pragma unroll 8
    for (int kk = 0; kk < 80; kk++) {
        float a[4], bb[4];
        #pragma unroll
        for (int i = 0; i < 4; i++) a[i] = Qs[ty * 4 + i][kk];
        #pragma unroll
        for (int j = 0; j < 4; j++) bb[j] = Ks[tx * 4 + j][kk];
        #pragma unroll
        for (int i = 0; i < 4; i++)
            #pragma unroll
            for (int j = 0; j < 4; j++)
                acc[i][j] = fmaf(a[i], bb[j], acc[i][j]);
    }
    #pragma unroll
    for (int i = 0; i < 4; i++)
        #pragma unroll
        for (int j = 0; j < 4; j++)
            scores[((size_t)bh * Ss + i0 + ty * 4 + i) * Ss + j0 + tx * 4 + j] =
                acc[i][j] * SCALE;
}

// ---------------- small bodies (identical numerics) ---------------------------
__device__ __forceinline__ void gather_body(
    const float* __restrict__ k, const float* __restrict__ v,
    const float* __restrict__ pos, float* __restrict__ tb, int r, int tid)
{
    const float* src = (r < 2048) ? k : v;
    int rr  = r & 2047;
    int b   = rr >> 10;
    int h   = (rr >> 5) & 31;
    int blk = rr & 31;
    for (int c = tid; c < Dm; c += 256) {
        int i = c / HD, d = c % HD;
        int s = blk * BS + i;
        tb[(size_t)r * Dm + c] =
            src[((size_t)(b * Ss + s)) * Dm + h * HD + d] + pos[c];
    }
}

__device__ __forceinline__ void gates_body(
    const float* __restrict__ gh, const float* __restrict__ W2,
    const float* __restrict__ b2, float* __restrict__ gates, int w, int lane)
{
    if (w >= ROWS * 3) return;
    int row = w / 3, j = w % 3;
    const float* g = gh + (size_t)row * (Dm / 2);
    float acc = 0.f;
    for (int c = lane; c < Dm / 2; c += 32) acc = fmaf(g[c], W2[c * 3 + j], acc);
    #pragma unroll
    for (int o = 16; o > 0; o >>= 1) acc += __shfl_xor_sync(0xffffffffu, acc, o);
    if (lane == 0) gates[w] = 1.f / (1.f + expf(-(acc + b2[j])));
}

__device__ __forceinline__ void outc_body(
    const float* __restrict__ q, const float* __restrict__ kcvc,
    const float* __restrict__ gates, float* __restrict__ combined, int idx)
{
    if (idx >= BH * Ss) return;
    int bh = idx >> 10;
    int s  = idx & 1023;
    int b  = bh >> 5, h = bh & 31;
    const float* qrow = q + ((size_t)(b * Ss + s)) * Dm + h * HD;
    const float* kc   = kcvc + (size_t)bh * NBLK * HD;
    const float* vc   = kcvc + (size_t)2048 * HD + (size_t)bh * NBLK * HD;

    float logit[NBLK];
    float mx = -INFINITY;
    #pragma unroll
    for (int j = 0; j < NBLK; j++) {
        float acc = 0.f;
        const float* kr = kc + j * HD;
        for (int d = 0; d < HD; d++) acc = fmaf(qrow[d], kr[d], acc);
        acc *= SCALE;
        logit[j] = acc;
        mx = fmaxf(mx, acc);
    }
    float Z = 0.f;
    #pragma unroll
    for (int j = 0; j < NBLK; j++) { logit[j] = expf(logit[j] - mx); Z += logit[j]; }
    float g0 = gates[(b * Ss + s) * 3 + 0];
    float c0 = g0 / Z;
    float* out = combined + ((size_t)(b * Ss + s)) * Dm + h * HD;
    for (int d = 0; d < HD; d++) {
        float acc = 0.f;
        #pragma unroll
        for (int j = 0; j < NBLK; j++) acc = fmaf(logit[j], vc[j * HD + d], acc);
        out[d] = c0 * acc;
    }
}

__device__ __forceinline__ void mask_body(
    const float* __restrict__ scores, unsigned* __restrict__ mask, int idx)
{
    int gw   = idx >> 5;
    int lane = idx & 31;
    if (gw >= BH * Ss) return;
    const float* row = scores + (size_t)gw * Ss;
    float s = 0.f;
    for (int t = 0; t < BS; t++) s += row[lane * BS + t];

    unsigned m = 0;
    float val = s;
    for (int it = 0; it < KTOP; it++) {
        float bv = val; int bi = lane;
        #pragma unroll
        for (int off = 16; off > 0; off >>= 1) {
            float ov = __shfl_xor_sync(0xffffffffu, bv, off);
            int   oi = __shfl_xor_sync(0xffffffffu, bi, off);
            if (ov > bv || (ov == bv && oi < bi)) { bv = ov; bi = oi; }
        }
        m |= (1u << bi);
        if (lane == bi) val = -INFINITY;
    }
    if (lane == 0) mask[gw] = m;
}

__device__ __forceinline__ void weights_body(
    float* __restrict__ scores, const unsigned* __restrict__ mask,
    const float* __restrict__ gates, int row, int tid, char* smraw)
{
    float* sm  = reinterpret_cast<float*>(smraw);          // [1024]
    float* red = sm + Ss;                                  // [256]
    int bh  = row >> 10;
    int s   = row & 1023;
    int b   = bh >> 5;
    float* rp = scores + (size_t)row * Ss;
    unsigned msk = mask[row];

    float lmw = -INFINITY;
    for (int c = tid; c < Ss; c += 256) {
        float x = rp[c];
        sm[c] = x;
        lmw = fmaxf(lmw, x);
    }
    red[tid] = lmw; __syncthreads();
    for (int st = 128; st > 0; st >>= 1) {
        if (tid < st) red[tid] = fmaxf(red[tid], red[tid + st]);
        __syncthreads();
    }
    float mw = red[0]; __syncthreads();

    float lzw = 0.f, lzs = 0.f;
    for (int c = tid; c < Ss; c += 256) {
        float ew = expf(sm[c] - mw);
        sm[c] = ew;
        lzw += ew;
        if ((msk >> (c >> 5)) & 1u) lzs += ew;
    }
    red[tid] = lzw; __syncthreads();
    for (int st = 128; st > 0; st >>= 1) {
        if (tid < st) red[tid] += red[tid + st];
        __syncthreads();
    }
    float Zw = red[0]; __syncthreads();
    red[tid] = lzs; __syncthreads();
    for (int st = 128; st > 0; st >>= 1) {
        if (tid < st) red[tid] += red[tid + st];
        __syncthreads();
    }
    float Zs = red[0]; __syncthreads();

    float g1 = gates[(b * Ss + s) * 3 + 1];
    float g2 = gates[(b * Ss + s) * 3 + 2];
    float cw = g2 / Zw;
    float cs = g1 / Zs;
    for (int c = tid; c < Ss; c += 256) {
        float ew = sm[c];
        float w = cw * ew;
        if ((msk >> (c >> 5)) & 1u) w += cs * ew;
        rp[c] = w;
    }
}

// =====================================================================
// FAT kernels — block-type dispatch for pipe-level overlap.
// =====================================================================

// FAT1: Wq/Wk SIMT (640 tiles) interleaved 4:3 with Wv/gate MMA (480 tiles)
__global__ void __launch_bounds__(256, 2) fat1_kernel(
    const float* __restrict__ hidden,
    const float* __restrict__ Wq, const float* __restrict__ bq,
    const float* __restrict__ Wk, const float* __restrict__ bk,
    const float* __restrict__ Wv, const float* __restrict__ bv,
    const float* __restrict__ gW1, const float* __restrict__ gb1,
    float* __restrict__ q, float* __restrict__ k,
    float* __restrict__ v, float* __restrict__ gh)
{
    __shared__ __align__(16) char smraw[MMA_SMEM_BYTES];
    int bid = blockIdx.x, tid = threadIdx.x;
    int grp = bid / 7, rem = bid % 7;
    if (rem < 4) {
        int s = grp * 4 + rem;                   // 0..639 SIMT tiles
        if (s < 320)
            simt_tile(hidden, Wq, bq, q, Dm, Dm, (s / 20) * 128, (s % 20) * 128, ACT_NONE, tid, smraw);
        else {
            s -= 320;
            simt_tile(hidden, Wk, bk, k, Dm, Dm, (s / 20) * 128, (s % 20) * 128, ACT_NONE, tid, smraw);
        }
    } else {
        int m = grp * 3 + (rem - 4);             // 0..479 MMA tiles
        if (m < 320)
            mma_tile(hidden, Wv, bv, v, Dm, Dm, Dm, Dm, Dm,
                     (m / 20) * 128, (m % 20) * 128, 1.f, ACT_NONE, 0, tid, smraw);
        else {
            m -= 320;
            mma_tile(hidden, gW1, gb1, gh, Dm / 2, Dm, Dm, Dm / 2, Dm / 2,
                     (m / 10) * 128, (m % 10) * 128, 1.f, ACT_GELU, 0, tid, smraw);
        }
    }
}

// gather + gates
__global__ void __launch_bounds__(256) gg_kernel(
    const float* __restrict__ k, const float* __restrict__ v,
    const float* __restrict__ pos, float* __restrict__ tb,
    const float* __restrict__ gh, const float* __restrict__ W2,
    const float* __restrict__ b2, float* __restrict__ gates)
{
    int bid = blockIdx.x, tid = threadIdx.x;
    if (bid < 4096) gather_body(k, v, pos, tb, bid, tid);
    else            gates_body(gh, W2, b2, gates, (((bid - 4096) * 256 + tid) >> 5), tid & 31);
}

// FAT2: compW1 MMA (96 tiles) + scores SIMT (16384 tiles)
__global__ void __launch_bounds__(256, 2) fat2_kernel(
    const float* __restrict__ tb, const float* __restrict__ cW1,
    const float* __restrict__ cb1, float* __restrict__ h1,
    const float* __restrict__ q, const float* __restrict__ k,
    float* __restrict__ scores)
{
    __shared__ __align__(16) char smraw[64 * 81 * 8];   // 41472 >= MMA_SMEM_BYTES
    int bid = blockIdx.x, tid = threadIdx.x;
    if (bid < 96) {
        mma_tile(tb, cW1, cb1, h1, 320, Dm, Dm, 320, 320,
                 (bid / 3) * 128, (bid % 3) * 128, 1.f, ACT_GELU, 0, tid, smraw);
    } else {
        int sid = bid - 96;
        int j0 = (sid & 15) * 64;
        int i0 = ((sid >> 4) & 15) * 64;
        int bh = sid >> 8;
        scores_tile(q, k, scores, bh, i0, j0, tid, smraw);
    }
}

// compW2 MMA (32 tiles) + mask (8192 blocks)
__global__ void __launch_bounds__(256, 2) cm_kernel(
    const float* __restrict__ h1, const float* __restrict__ cW2,
    const float* __restrict__ cb2, float* __restrict__ kcvc,
    const float* __restrict__ scores, unsigned* __restrict__ mask)
{
    __shared__ __align__(16) char smraw[MMA_SMEM_BYTES];
    int bid = blockIdx.x, tid = threadIdx.x;
    if (bid < 32)
        mma_tile(h1, cW2, cb2, kcvc, HD, 320, 320, HD, HD,
                 bid * 128, 0, 1.f, ACT_NONE, 0, tid, smraw);
    else
        mask_body(scores, mask, (bid - 32) * 256 + tid);
}

// outc (256 blocks) + weights (65536 blocks)
__global__ void __launch_bounds__(256) ow_kernel(
    const float* __restrict__ q, const float* __restrict__ kcvc,
    const float* __restrict__ gates, float* __restrict__ combined,
    float* __restrict__ scores, const unsigned* __restrict__ mask)
{
    __shared__ __align__(16) char smraw[(Ss + 256) * 4];
    int bid = blockIdx.x, tid = threadIdx.x;
    if (bid < 256) outc_body(q, kcvc, gates, combined, bid * 256 + tid);
    else           weights_body(scores, mask, gates, bid - 256, tid, smraw);
}

// standalone batched MMA wrapper (PV, Wo)
__global__ void __launch_bounds__(256, 2) mma_gemm_g(
    const float* __restrict__ A, const float* __restrict__ B,
    const float* __restrict__ bias, float* __restrict__ C,
    int N, int K, int lda, int ldb, int ldc,
    long long sAz, long long sAb, long long sBz, long long sBb,
    long long sCz, long long sCb, float alpha, int act, int beta1)
{
    __shared__ __align__(16) char smraw[MMA_SMEM_BYTES];
    int z = blockIdx.z;
    const float* Ap = A + (size_t)z * sAz + (size_t)(z >> 5) * sAb;
    const float* Bp = B + (size_t)z * sBz + (size_t)(z >> 5) * sBb;
    float*       Cp = C + (size_t)z * sCz + (size_t)(z >> 5) * sCb;
    mma_tile(Ap, Bp, bias, Cp, N, K, lda, ldb, ldc,
             blockIdx.y * 128, blockIdx.x * 128, alpha, act, beta1,
             threadIdx.x, smraw);
}

// ---------------- host launch ------------------------------------------------
static void* symaddr(const void* sym) {
    void* p = nullptr;
    cudaGetSymbolAddress(&p, sym);
    return p;
}

extern "C" void kernel_launch(void* const* d_in, const int* in_sizes, int n_in,
                              void* d_out, int out_size)
{
    const float* hidden  = (const float*)d_in[0];
    const float* Wq      = (const float*)d_in[1];
    const float* bq      = (const float*)d_in[2];
    const float* Wk      = (const float*)d_in[3];
    const float* bk      = (const float*)d_in[4];
    const float* Wv      = (const float*)d_in[5];
    const float* bv      = (const float*)d_in[6];
    const float* Wo      = (const float*)d_in[7];
    const float* bo      = (const float*)d_in[8];
    const float* cpos    = (const float*)d_in[9];
    const float* cW1     = (const float*)d_in[10];
    const float* cb1     = (const float*)d_in[11];
    const float* cW2     = (const float*)d_in[12];
    const float* cb2     = (const float*)d_in[13];
    const float* gW1     = (const float*)d_in[14];
    const float* gb1     = (const float*)d_in[15];
    const float* gW2     = (const float*)d_in[16];
    const float* gb2     = (const float*)d_in[17];
    float* out = (float*)d_out;

    float*    q     = (float*)symaddr(g_q);
    float*    k     = (float*)symaddr(g_k);
    float*    v     = (float*)symaddr(g_v);
    float*    gh    = (float*)symaddr(g_gh);
    float*    gates = (float*)symaddr(g_gates);
    float*    tb    = (float*)symaddr(g_tb);
    float*    h1    = (float*)symaddr(g_h1);
    float*    kcvc  = (float*)symaddr(g_kcvc);
    float*    sc    = (float*)symaddr(g_scores);
    unsigned* msk   = (unsigned*)symaddr(g_mask);
    float*    comb  = (float*)symaddr(g_comb);

    const long long sQh = HD;                           // per-z (head) offset
    const long long sQb = (long long)Ss * Dm - 32 * HD; // per-batch extra

    // Phase 1: Wq/Wk (SIMT, top-k path) overlapped with Wv/gate (bf16 MMA)
    fat1_kernel<<<1120, 256>>>(hidden, Wq, bq, Wk, bk, Wv, bv, gW1, gb1, q, k, v, gh);

    // Phase 2: comp gather + gate sigmoid
    gg_kernel<<<4096 + 768, 256>>>(k, v, cpos, tb, gh, gW2, gb2, gates);

    // Phase 3: compW1 (MMA) overlapped with dense scores (SIMT, validated)
    fat2_kernel<<<96 + 16384, 256>>>(tb, cW1, cb1, h1, q, k, sc);

    // Phase 4: compW2 (MMA) + block top-k mask
    cm_kernel<<<32 + 8192, 256>>>(h1, cW2, cb2, kcvc, sc, msk);

    // Phase 5: compressed branch output + fused dual-softmax weights
    ow_kernel<<<256 + 65536, 256>>>(q, kcvc, gates, comb, sc, msk);

    // Phase 6: PV (batched, accumulate into comb)
    mma_gemm_g<<<dim3(1, Ss / 128, BH), 256>>>(
        sc, v, nullptr, comb, HD, Ss, Ss, Dm, Dm,
        (long long)Ss * Ss, 0, sQh, sQb, sQh, sQb, 1.f, ACT_NONE, 1);

    // Phase 7: output projection
    mma_gemm_g<<<dim3(Dm / 128, ROWS / 128, 1), 256>>>(
        comb, Wo, bo, out, Dm, Dm, Dm, Dm, Dm,
        0, 0, 0, 0, 0, 0, 1.f, ACT_NONE, 0);
}